// round 11
// baseline (speedup 1.0000x reference)
#include <cuda_runtime.h>
#include <cuda_bf16.h>
#include <mma.h>
#include <math.h>

// ---------------- problem constants ----------------
#define NFFT    1881
#define STEPSZ  941
#define ZB      109
#define NFRAMES 468
#define NBATCH  8
#define MTOT    (NBATCH*NFRAMES)
#define MPAD    3840
#define NBINS   765
#define TLEN    441000
#define LOG2_10 3.321928094887362f
#define KLO     20
#define KHI     71
#define KWIN    (KHI-KLO)
#define RS      24
// CT factorization: 1881 = 9 x 209
#define N2CNT   209
#define KP2     432            // 2*209 = 418 padded to 432 (27 x 16)
#define NT2     (KP2/16)       // 27
#define NCLS    9
#define NPC     192            // per-class N: 85 bins x2 padded to 192
#define ROWW    (NCLS*NPC)     // 1728 floats per CM row
#define BM      64             // gemm M tile

// fast transcendentals: MUFU-based (no inline asm)
__device__ __forceinline__ float fexp2(float x) { return __expf(x * 0.6931471805599453f); }

// ---------------- scratch (static device memory; no allocations) ----------------
__device__ __align__(16) __nv_bfloat16 g_Ah[(size_t)NCLS * MPAD * KP2];
__device__ __align__(16) __nv_bfloat16 g_Al[(size_t)NCLS * MPAD * KP2];
__device__ __align__(16) __nv_bfloat16 g_Bh[NCLS * NPC * KP2];
__device__ __align__(16) __nv_bfloat16 g_Bl[NCLS * NPC * KP2];
__device__ __align__(16) float g_CM[(size_t)MPAD * ROWW];
__device__ __align__(16) float g_BARK[NBINS * 112];
__device__ __align__(16) float g_UEP[MTOT * 112];
__device__ __align__(16) float g_SM[NBATCH * ZB * NFRAMES];
__device__ __align__(16) float2 g_TRIG[NFFT];
__device__ __align__(16) float g_CALSW[10 * NFFT];
__device__ float g_ESC[NBINS];
__device__ float g_W[NFFT];
__device__ float g_FC[ZB], g_SU0[ZB], g_WN[ZB], g_A[ZB], g_NORMI[ZB];
__device__ float g_FMAG[10 * KWIN];
__device__ float g_FAC[1];

// ---------------- setup A: tables (grid-strided, multi-block) ----------------
__global__ void k_tab() {
    int gt = blockIdx.x * blockDim.x + threadIdx.x;
    int gs = gridDim.x * blockDim.x;
    for (int n = gt; n < NFFT; n += gs)
        g_W[n] = (float)(0.5 * (1.0 - cospi(2.0 * n / 1880.0)));
    for (int m = gt; m < NFFT; m += gs) {
        double ph = 2.0 * (double)m / 1881.0;
        g_TRIG[m] = make_float2((float)cospi(ph), (float)sinpi(ph));
    }
    for (int i = gt; i < 10 * NFFT; i += gs) {
        int fr = i / NFFT, n = i % NFFT;
        int t = fr * STEPSZ + n;
        int p = (t * 2039) % 88200;
        float sv = sinpif((float)p * (1.0f / 44100.0f));
        float wp = 0.5f * (1.0f - cospif((float)(2 * n) * (1.0f / 1881.0f)));
        g_CALSW[i] = wp * sv;
    }
    for (int j = gt; j < NBINS; j += gs) {
        int bin = j + 3;
        float f = 22050.0f * (float)bin / 941.0f;
        float fk = f * 0.001f;
        float lgfk = log2f(fk);
        float Wdb = -2.184f * exp2f(-0.8f * lgfk)
                  + 6.5f * expf(-0.6f * (fk - 3.3f) * (fk - 3.3f))
                  - 0.001f * exp2f(3.6f * lgfk);
        g_ESC[j] = exp2f(Wdb * (LOG2_10 / 20.f)) * (1.0f / 1881.0f);
    }
    if (gt < ZB) {
        double zL = 7.0 * asinh(80.0 / 650.0);
        double ze = zL + 0.25 * gt;
        double fcd = 650.0 * sinh((ze + 0.125) / 7.0);
        float fc = (float)fcd;
        g_FC[gt] = fc;
        g_SU0[gt] = -24.0f - 230.0f / fc;
        g_WN[gt] = (float)pow(10.0, 0.4 * 0.364 * pow(fcd / 1000.0, -0.8));
        double tau = 0.008 + 2.2 / fcd;
        g_A[gt] = (float)exp(-4.0 / (187.5 * tau));
    }
}

// ---------------- setup B: Ec-based norm_inv (needs SU0) ----------------
__global__ void k_norm() {
    int tid = threadIdx.x;
    __shared__ float srow[ZB];
    if (tid < ZB) {
        int r = tid; float s = 0.f;
        for (int c = 0; c < ZB; c++) {
            float slope = (r <= c) ? 27.0f : g_SU0[r];
            float e = fminf(0.025f * (float)(r - c) * slope, 30.0f);
            s += fexp2(e * LOG2_10);
        }
        srow[r] = s;
    }
    __syncthreads();
    if (tid < ZB) {
        int r = tid; float t = 0.f;
        for (int c = 0; c < ZB; c++) {
            float slope = (r <= c) ? 27.0f : g_SU0[r];
            float e = fminf(0.025f * (float)(r - c) * slope, 30.0f);
            float ec = fexp2(e * LOG2_10) / srow[c];
            t += fexp2(0.4f * __log2f(ec));
        }
        g_NORMI[r] = fexp2(-2.5f * __log2f(t));
    }
}

// ---------------- setup: bark overlap matrix (fp64, faithful) ----------------
__global__ void k_barkmat() {
    int idx = blockIdx.x * blockDim.x + threadIdx.x;
    if (idx >= NBINS * ZB) return;
    int k = idx / ZB, j = idx % ZB;
    double df = 44100.0 / 1881.0;
    int bin = k + 3;
    double blo = bin * df - df / 2.0, bhi = bin * df + df / 2.0;
    double zL = 7.0 * asinh(80.0 / 650.0);
    double felo = 650.0 * sinh((zL + 0.25 * j) / 7.0);
    double fehi = 650.0 * sinh((zL + 0.25 * (j + 1)) / 7.0);
    double ov = fmin(bhi, fehi) - fmax(blo, felo);
    ov = fmax(ov, 0.0) / df;
    g_BARK[k * 112 + j] = (float)ov;
}

// ---------------- setup: FAC calibration (peak near bin 43.5) ----------------
__global__ void k_facmag() {
    int k = blockIdx.x + KLO;
    int fr = blockIdx.y;
    int tid = threadIdx.x;
    const float* sw = &g_CALSW[fr * NFFT];
    float re = 0.f, im = 0.f;
    for (int n = tid; n < NFFT; n += 128) {
        int m = (k * n) % NFFT;
        float2 t = g_TRIG[m];
        float wx = sw[n];
        re += wx * t.x;
        im += wx * t.y;
    }
    __shared__ float sre[128], sim[128];
    sre[tid] = re; sim[tid] = im; __syncthreads();
    for (int o = 64; o > 0; o >>= 1) {
        if (tid < o) { sre[tid] += sre[tid + o]; sim[tid] += sim[tid + o]; }
        __syncthreads();
    }
    if (tid == 0) g_FMAG[fr * KWIN + blockIdx.x] = sqrtf(sre[0] * sre[0] + sim[0] * sim[0]);
}

__global__ void k_facred() {
    int w = threadIdx.x >> 5, lane = threadIdx.x & 31;
    __shared__ float fmx[10];
    if (w < 10) {
        float mx = 0.f;
        for (int k = lane; k < KWIN; k += 32) mx = fmaxf(mx, g_FMAG[w * KWIN + k]);
        for (int o = 16; o > 0; o >>= 1) mx = fmaxf(mx, __shfl_xor_sync(0xffffffff, mx, o));
        if (lane == 0) fmx[w] = mx;
    }
    __syncthreads();
    if (threadIdx.x == 0) {
        float total = 0.f;
        for (int fr = 0; fr < 10; fr++) total += fmx[fr];
        g_FAC[0] = exp2f(4.6f * LOG2_10) / (total * 0.1f);
    }
}

// ---------------- setup: per-class twiddle matrices B (split bf16 hi/lo) ----------------
// NOTE: FAC is NOT folded here (applied as FAC^2 in k_bark) so tw2 only needs g_TRIG/g_ESC.
__global__ void k_tw2() {
    int gid = blockIdx.x;           // 0 .. 9*192-1
    int c = gid / NPC, col = gid - c * NPC;
    int p = col >> 1;
    int k0 = (c >= 3) ? c : c + 9;
    int k = k0 + 9 * p;
    bool valid = (p < 85);
    float sc = valid ? g_ESC[k - 3] : 0.f;
    for (int q = threadIdx.x; q < KP2; q += 128) {
        float v = 0.f;
        if (valid && q < 2 * N2CNT) {
            int n2 = q >> 1;
            float2 t = g_TRIG[(k * n2) % NFFT];
            if ((col & 1) == 0) v = (q & 1) ? t.y : t.x;
            else                v = (q & 1) ? t.x : -t.y;
            v *= sc;
        }
        __nv_bfloat16 h = __float2bfloat16(v);
        float r = v - __bfloat162float(h);
        size_t o = ((size_t)c * NPC + col) * KP2 + q;
        g_Bh[o] = h;
        g_Bl[o] = __float2bfloat16(r);
    }
}

// ---------------- stage 1: window + 9-point fold -> A (split bf16 hi/lo) ----------------
__global__ void k_fold(const float* __restrict__ pred, const float* __restrict__ targ) {
    __shared__ float xw[NFFT];
    int fg = blockIdx.x;
    int tid = threadIdx.x;          // 256
    int b = fg / NFRAMES, f = fg % NFRAMES;
    const float* src = (b < 4) ? pred + (size_t)b * TLEN : targ + (size_t)(b - 4) * TLEN;
    int start = f * STEPSZ;
    for (int n = tid; n < NFFT; n += 256) {
        int s = start + n;
        xw[n] = ((s < TLEN) ? src[s] : 0.f) * g_W[n];
    }
    __syncthreads();
    for (int idx = tid; idx < NFFT; idx += 256) {
        int c = idx / N2CNT;
        int n2 = idx - c * N2CNT;
        float yr = 0.f, yi = 0.f;
        for (int n1 = 0; n1 < 9; n1++) {
            int m = ((c * n1) % 9) * N2CNT;
            float2 t = g_TRIG[m];
            float xv = xw[n2 + N2CNT * n1];
            yr = fmaf(xv, t.x, yr);
            yi = fmaf(-xv, t.y, yi);
        }
        size_t base = ((size_t)c * MPAD + fg) * KP2 + 2 * n2;
        __nv_bfloat16 hr = __float2bfloat16(yr);
        __nv_bfloat16 hiq = __float2bfloat16(yi);
        g_Ah[base] = hr;
        g_Ah[base + 1] = hiq;
        g_Al[base] = __float2bfloat16(yr - __bfloat162float(hr));
        g_Al[base + 1] = __float2bfloat16(yi - __bfloat162float(hiq));
    }
    if (tid < KP2 - 2 * N2CNT) {
        __nv_bfloat16 z = __float2bfloat16(0.f);
        for (int c = 0; c < NCLS; c++) {
            size_t base = ((size_t)c * MPAD + fg) * KP2 + 2 * N2CNT + tid;
            g_Ah[base] = z;
            g_Al[base] = z;
        }
    }
}

// ---------------- stage 2: split-bf16 tensor GEMM per class ----------------
// block 64M x 192N, 8 warps = 2m x 4n, warp tile 32x48 (2 blocks/SM)
__global__ __launch_bounds__(256, 2) void k_gemm2() {
    using namespace nvcuda;
    __shared__ __align__(16) __nv_bfloat16 sAh[BM][RS];
    __shared__ __align__(16) __nv_bfloat16 sAl[BM][RS];
    __shared__ __align__(16) __nv_bfloat16 sBh[NPC][RS];
    __shared__ __align__(16) __nv_bfloat16 sBl[NPC][RS];

    const int tid = threadIdx.x;
    const int w = tid >> 5;
    const int wm = w & 1;
    const int wn = w >> 1;
    const int cls = blockIdx.z;
    const int row0 = blockIdx.y * BM;

    const bool hasA = (tid < 128);
    const int lrA = tid >> 1;
    const int lh = (tid & 1) * 8;
    const size_t aoff = ((size_t)cls * MPAD + row0 + (hasA ? lrA : 0)) * KP2 + lh;
    const int lrB0 = tid >> 1;
    const size_t boff0 = ((size_t)cls * NPC + lrB0) * KP2 + lh;
    const int lrB1 = 128 + (tid >> 1);
    const size_t boff1 = ((size_t)cls * NPC + (hasA ? lrB1 : 128)) * KP2 + lh;

    uint4 rah = make_uint4(0, 0, 0, 0), ral = rah, rbh1 = rah, rbl1 = rah;
    if (hasA) {
        rah = *(const uint4*)(g_Ah + aoff);
        ral = *(const uint4*)(g_Al + aoff);
        rbh1 = *(const uint4*)(g_Bh + boff1);
        rbl1 = *(const uint4*)(g_Bl + boff1);
    }
    uint4 rbh0 = *(const uint4*)(g_Bh + boff0);
    uint4 rbl0 = *(const uint4*)(g_Bl + boff0);

    wmma::fragment<wmma::accumulator, 16, 16, 16, float> acc[2][3];
    for (int i = 0; i < 2; i++) {
        for (int j = 0; j < 3; j++) wmma::fill_fragment(acc[i][j], 0.f);
    }

    for (int kt = 0; kt < NT2; kt++) {
        __syncthreads();
        if (hasA) {
            *(uint4*)(&sAh[lrA][lh]) = rah;
            *(uint4*)(&sAl[lrA][lh]) = ral;
            *(uint4*)(&sBh[lrB1][lh]) = rbh1;
            *(uint4*)(&sBl[lrB1][lh]) = rbl1;
        }
        *(uint4*)(&sBh[lrB0][lh]) = rbh0;
        *(uint4*)(&sBl[lrB0][lh]) = rbl0;
        __syncthreads();
        if (kt + 1 < NT2) {
            size_t kk = (size_t)(kt + 1) * 16;
            if (hasA) {
                rah = *(const uint4*)(g_Ah + aoff + kk);
                ral = *(const uint4*)(g_Al + aoff + kk);
                rbh1 = *(const uint4*)(g_Bh + boff1 + kk);
                rbl1 = *(const uint4*)(g_Bl + boff1 + kk);
            }
            rbh0 = *(const uint4*)(g_Bh + boff0 + kk);
            rbl0 = *(const uint4*)(g_Bl + boff0 + kk);
        }

        wmma::fragment<wmma::matrix_b, 16, 16, 16, __nv_bfloat16, wmma::col_major> fbh[3], fbl[3];
        for (int ni = 0; ni < 3; ni++) {
            wmma::load_matrix_sync(fbh[ni], &sBh[wn * 48 + ni * 16][0], RS);
            wmma::load_matrix_sync(fbl[ni], &sBl[wn * 48 + ni * 16][0], RS);
        }
        for (int mi = 0; mi < 2; mi++) {
            wmma::fragment<wmma::matrix_a, 16, 16, 16, __nv_bfloat16, wmma::row_major> fah, fal;
            wmma::load_matrix_sync(fah, &sAh[wm * 32 + mi * 16][0], RS);
            wmma::load_matrix_sync(fal, &sAl[wm * 32 + mi * 16][0], RS);
            for (int ni = 0; ni < 3; ni++) {
                wmma::mma_sync(acc[mi][ni], fah, fbh[ni], acc[mi][ni]);
                wmma::mma_sync(acc[mi][ni], fah, fbl[ni], acc[mi][ni]);
                wmma::mma_sync(acc[mi][ni], fal, fbh[ni], acc[mi][ni]);
            }
        }
    }

    for (int mi = 0; mi < 2; mi++) {
        for (int ni = 0; ni < 3; ni++) {
            size_t r = (size_t)(row0 + wm * 32 + mi * 16);
            size_t cc = (size_t)(cls * NPC + wn * 48 + ni * 16);
            wmma::store_matrix_sync(&g_CM[r * ROWW + cc], acc[mi][ni], ROWW, wmma::mem_row_major);
        }
    }
}

// ---------------- |X|^2 (x FAC^2) -> bark energies (+ internal noise) ----------------
__global__ void k_bark() {
    int fb = blockIdx.x;
    int tid = threadIdx.x;
    __shared__ float P[8][768];
    float fac = g_FAC[0];
    float fac2 = fac * fac;
    for (int i = 0; i < 8; i++) {
        int fg = fb * 8 + i;
        const float* crow = &g_CM[(size_t)fg * ROWW];
        for (int j = tid; j < NBINS; j += 128) {
            int k = j + 3;
            int c = k % 9;
            int k0 = (c >= 3) ? c : c + 9;
            int p = (k - k0) / 9;
            float2 v = *(const float2*)&crow[c * NPC + 2 * p];
            P[i][j] = v.x * v.x + v.y * v.y;
        }
    }
    __syncthreads();
    if (tid < ZB) {
        float acc[8] = {0, 0, 0, 0, 0, 0, 0, 0};
        for (int j = 0; j < NBINS; j++) {
            float bv = g_BARK[j * 112 + tid];
            for (int i = 0; i < 8; i++) acc[i] += P[i][j] * bv;
        }
        float wn = g_WN[tid];
        for (int i = 0; i < 8; i++)
            g_UEP[(size_t)(fb * 8 + i) * 112 + tid] = fmaxf(acc[i] * fac2, 1e-12f) + wn;
    }
}

// ---------------- frequency smearing (faithful; MUFU transcendentals) ----------------
__global__ void k_smear() {
    int fg = blockIdx.x;
    int tid = threadIdx.x;
    __shared__ float m2[ZB], Su[ZB], icol[ZB];
    if (tid < ZB) {
        float lg = __log2f(g_UEP[(size_t)fg * 112 + tid]);
        float L = 3.0102999566f * lg;
        m2[tid] = fminf(0.30102999566f * lg, 30.0f);
        Su[tid] = g_SU0[tid] + 0.2f * L;
    }
    __syncthreads();
    if (tid < ZB) {
        int c = tid;
        float colsum = 0.f;
        for (int r = 0; r < ZB; r++) {
            float slope = (r <= c) ? 27.0f : Su[r];
            float e1 = 0.025f * (float)(r - c) * slope;
            float m = fminf(e1, 30.0f) + m2[r];
            colsum += fexp2(m * LOG2_10);
        }
        icol[c] = fexp2(-0.4f * __log2f(colsum));
    }
    __syncthreads();
    if (tid < ZB) {
        int c = tid;
        float acc = 0.f;
        for (int r = 0; r < ZB; r++) {
            float slope = (r <= c) ? 27.0f : Su[r];
            float e1 = 0.025f * (float)(r - c) * slope;
            float m = fminf(e1, 30.0f) + m2[r];
            acc += fexp2(0.4f * LOG2_10 * m) * icol[r];
        }
        float E2 = fexp2(2.5f * __log2f(acc)) * g_NORMI[c];
        int b = fg / NFRAMES, f = fg % NFRAMES;
        g_SM[((size_t)b * ZB + c) * NFRAMES + f] = E2;
    }
}

// ---------------- per-band IIR + max ----------------
__global__ void k_iir(float* __restrict__ out) {
    int idx = blockIdx.x * blockDim.x + threadIdx.x;
    if (idx >= NBATCH * ZB) return;
    int z = idx % ZB;
    float a = g_A[z], b0 = 1.f - a;
    const float* row = &g_SM[(size_t)idx * NFRAMES];
    float* orow = &out[(size_t)idx * NFRAMES];
    float ef = 0.f;
    for (int t = 0; t < NFRAMES; t++) {
        float u = row[t];
        float xin = (t == 0) ? 0.f : u;
        ef = fmaf(a, ef, b0 * xin);
        orow[t] = fmaxf(ef, u);
    }
}

// ---------------- launch ----------------
extern "C" void kernel_launch(void* const* d_in, const int* in_sizes, int n_in,
                              void* d_out, int out_size) {
    const float* pred = (const float*)d_in[0];
    const float* targ = (const float*)d_in[1];
    float* out = (float*)d_out;

    k_tab<<<64, 256>>>();
    k_tw2<<<NCLS * NPC, 128>>>();
    k_fold<<<MTOT, 256>>>(pred, targ);
    k_gemm2<<<dim3(1, MPAD / BM, NCLS), 256>>>();   // 4th launch -> profiled slot
    k_facmag<<<dim3(KWIN, 10), 128>>>();
    k_facred<<<1, 320>>>();
    k_norm<<<1, 128>>>();
    k_barkmat<<<(NBINS * ZB + 255) / 256, 256>>>();
    k_bark<<<NFRAMES, 128>>>();
    k_smear<<<MTOT, 128>>>();
    k_iir<<<(NBATCH * ZB + 127) / 128, 128>>>(out);
}

// round 12
// speedup vs baseline: 1.0720x; 1.0720x over previous
#include <cuda_runtime.h>
#include <cuda_bf16.h>
#include <cuda_pipeline_primitives.h>
#include <mma.h>
#include <math.h>

// ---------------- problem constants ----------------
#define NFFT    1881
#define STEPSZ  941
#define ZB      109
#define NFRAMES 468
#define NBATCH  8
#define MTOT    (NBATCH*NFRAMES)
#define MPAD    3840
#define NBINS   765
#define TLEN    441000
#define LOG2_10 3.321928094887362f
#define KLO     20
#define KHI     71
#define KWIN    (KHI-KLO)
#define RS      24
// CT factorization: 1881 = 9 x 209
#define N2CNT   209
#define KP2     432            // 2*209 = 418 padded to 432 (27 x 16)
#define NT2     (KP2/16)       // 27
#define NCLS    9
#define NPC     192            // per-class N: 85 bins x2 padded to 192
#define ROWW    (NCLS*NPC)     // 1728 floats per CM row
#define BM      64             // gemm M tile

// fast transcendentals: MUFU-based (no inline asm)
__device__ __forceinline__ float fexp2(float x) { return __expf(x * 0.6931471805599453f); }

// ---------------- scratch (static device memory; no allocations) ----------------
__device__ __align__(16) __nv_bfloat16 g_Ah[(size_t)NCLS * MPAD * KP2];
__device__ __align__(16) __nv_bfloat16 g_Al[(size_t)NCLS * MPAD * KP2];
__device__ __align__(16) __nv_bfloat16 g_Bh[NCLS * NPC * KP2];
__device__ __align__(16) __nv_bfloat16 g_Bl[NCLS * NPC * KP2];
__device__ __align__(16) float g_CM[(size_t)MPAD * ROWW];
__device__ __align__(16) float g_BARK[NBINS * 112];
__device__ __align__(16) float g_UEP[MTOT * 112];
__device__ __align__(16) float g_SM[NBATCH * ZB * NFRAMES];
__device__ __align__(16) float2 g_TRIG[NFFT];
__device__ __align__(16) float g_CALSW[10 * NFFT];
__device__ float g_ESC[NBINS];
__device__ float g_W[NFFT];
__device__ float g_FC[ZB], g_SU0[ZB], g_WN[ZB], g_A[ZB], g_NORMI[ZB];
__device__ float g_FMAG[10 * KWIN];
__device__ float g_FAC[1];

// ---------------- setup A: tables + bark overlap matrix (grid-strided) ----------------
__global__ void k_tab() {
    int gt = blockIdx.x * blockDim.x + threadIdx.x;
    int gs = gridDim.x * blockDim.x;
    for (int n = gt; n < NFFT; n += gs)
        g_W[n] = (float)(0.5 * (1.0 - cospi(2.0 * n / 1880.0)));
    for (int m = gt; m < NFFT; m += gs) {
        double ph = 2.0 * (double)m / 1881.0;
        g_TRIG[m] = make_float2((float)cospi(ph), (float)sinpi(ph));
    }
    for (int i = gt; i < 10 * NFFT; i += gs) {
        int fr = i / NFFT, n = i % NFFT;
        int t = fr * STEPSZ + n;
        int p = (t * 2039) % 88200;
        float sv = sinpif((float)p * (1.0f / 44100.0f));
        float wp = 0.5f * (1.0f - cospif((float)(2 * n) * (1.0f / 1881.0f)));
        g_CALSW[i] = wp * sv;
    }
    for (int j = gt; j < NBINS; j += gs) {
        int bin = j + 3;
        float f = 22050.0f * (float)bin / 941.0f;
        float fk = f * 0.001f;
        float lgfk = log2f(fk);
        float Wdb = -2.184f * exp2f(-0.8f * lgfk)
                  + 6.5f * expf(-0.6f * (fk - 3.3f) * (fk - 3.3f))
                  - 0.001f * exp2f(3.6f * lgfk);
        g_ESC[j] = exp2f(Wdb * (LOG2_10 / 20.f)) * (1.0f / 1881.0f);
    }
    // bark overlap matrix (fp64, faithful)
    for (int idx = gt; idx < NBINS * ZB; idx += gs) {
        int k = idx / ZB, j = idx % ZB;
        double df = 44100.0 / 1881.0;
        int bin = k + 3;
        double blo = bin * df - df / 2.0, bhi = bin * df + df / 2.0;
        double zL = 7.0 * asinh(80.0 / 650.0);
        double felo = 650.0 * sinh((zL + 0.25 * j) / 7.0);
        double fehi = 650.0 * sinh((zL + 0.25 * (j + 1)) / 7.0);
        double ov = fmin(bhi, fehi) - fmax(blo, felo);
        ov = fmax(ov, 0.0) / df;
        g_BARK[k * 112 + j] = (float)ov;
    }
    if (gt < ZB) {
        double zL = 7.0 * asinh(80.0 / 650.0);
        double ze = zL + 0.25 * gt;
        double fcd = 650.0 * sinh((ze + 0.125) / 7.0);
        float fc = (float)fcd;
        g_FC[gt] = fc;
        g_SU0[gt] = -24.0f - 230.0f / fc;
        g_WN[gt] = (float)pow(10.0, 0.4 * 0.364 * pow(fcd / 1000.0, -0.8));
        double tau = 0.008 + 2.2 / fcd;
        g_A[gt] = (float)exp(-4.0 / (187.5 * tau));
    }
}

// ---------------- setup: per-class twiddle matrices B (split bf16 hi/lo) ----------------
// FAC not folded (applied as FAC^2 in k_bark).
__global__ void k_tw2() {
    int gid = blockIdx.x;           // 0 .. 9*192-1
    int c = gid / NPC, col = gid - c * NPC;
    int p = col >> 1;
    int k0 = (c >= 3) ? c : c + 9;
    int k = k0 + 9 * p;
    bool valid = (p < 85);
    float sc = valid ? g_ESC[k - 3] : 0.f;
    for (int q = threadIdx.x; q < KP2; q += 128) {
        float v = 0.f;
        if (valid && q < 2 * N2CNT) {
            int n2 = q >> 1;
            float2 t = g_TRIG[(k * n2) % NFFT];
            if ((col & 1) == 0) v = (q & 1) ? t.y : t.x;
            else                v = (q & 1) ? t.x : -t.y;
            v *= sc;
        }
        __nv_bfloat16 h = __float2bfloat16(v);
        float r = v - __bfloat162float(h);
        size_t o = ((size_t)c * NPC + col) * KP2 + q;
        g_Bh[o] = h;
        g_Bl[o] = __float2bfloat16(r);
    }
}

// ---------------- stage 1: window + 9-point fold -> A (split bf16 hi/lo) ----------------
// c-outer / n2-inner: no div-mod, hoisted twiddles, coalesced 4-byte bf16x2 stores.
__global__ void k_fold(const float* __restrict__ pred, const float* __restrict__ targ) {
    __shared__ float xw[NFFT];
    int fg = blockIdx.x;
    int tid = threadIdx.x;          // 256
    int b = fg / NFRAMES, f = fg % NFRAMES;
    const float* src = (b < 4) ? pred + (size_t)b * TLEN : targ + (size_t)(b - 4) * TLEN;
    int start = f * STEPSZ;
    for (int n = tid; n < NFFT; n += 256) {
        int s = start + n;
        xw[n] = ((s < TLEN) ? src[s] : 0.f) * g_W[n];
    }
    __syncthreads();
    for (int c = 0; c < NCLS; c++) {
        float2 tw[9];
        #pragma unroll
        for (int n1 = 0; n1 < 9; n1++)
            tw[n1] = g_TRIG[((c * n1) % 9) * N2CNT];
        for (int n2 = tid; n2 < N2CNT; n2 += 256) {
            float yr = 0.f, yi = 0.f;
            #pragma unroll
            for (int n1 = 0; n1 < 9; n1++) {
                float xv = xw[n2 + N2CNT * n1];
                yr = fmaf(xv, tw[n1].x, yr);
                yi = fmaf(-xv, tw[n1].y, yi);
            }
            size_t base = ((size_t)c * MPAD + fg) * KP2 + 2 * n2;
            __nv_bfloat162 h2;
            h2.x = __float2bfloat16(yr);
            h2.y = __float2bfloat16(yi);
            *(__nv_bfloat162*)(g_Ah + base) = h2;
            __nv_bfloat162 l2;
            l2.x = __float2bfloat16(yr - __bfloat162float(h2.x));
            l2.y = __float2bfloat16(yi - __bfloat162float(h2.y));
            *(__nv_bfloat162*)(g_Al + base) = l2;
        }
    }
    if (tid < KP2 - 2 * N2CNT) {
        __nv_bfloat16 z = __float2bfloat16(0.f);
        for (int c = 0; c < NCLS; c++) {
            size_t base = ((size_t)c * MPAD + fg) * KP2 + 2 * N2CNT + tid;
            g_Ah[base] = z;
            g_Al[base] = z;
        }
    }
}

// ---------------- stage 2: split-bf16 tensor GEMM, 2-stage cp.async, 1 sync/k-step ----
__global__ __launch_bounds__(256, 2) void k_gemm2() {
    using namespace nvcuda;
    __shared__ __align__(16) __nv_bfloat16 sAh[2][BM][RS];
    __shared__ __align__(16) __nv_bfloat16 sAl[2][BM][RS];
    __shared__ __align__(16) __nv_bfloat16 sBh[2][NPC][RS];
    __shared__ __align__(16) __nv_bfloat16 sBl[2][NPC][RS];

    const int tid = threadIdx.x;
    const int w = tid >> 5;
    const int wm = w & 1;           // 2 warp-rows -> 32 M each
    const int wn = w >> 1;          // 4 warp-cols -> 48 N each
    const int cls = blockIdx.z;
    const int row0 = blockIdx.y * BM;

    const bool hasA = (tid < 128);
    const int lrA = tid >> 1;
    const int lh = (tid & 1) * 8;
    const size_t aoff = ((size_t)cls * MPAD + row0 + (hasA ? lrA : 0)) * KP2 + lh;
    const int lrB0 = tid >> 1;
    const size_t boff0 = ((size_t)cls * NPC + lrB0) * KP2 + lh;
    const int lrB1 = 128 + (tid >> 1);
    const size_t boff1 = ((size_t)cls * NPC + (hasA ? lrB1 : 128)) * KP2 + lh;

    auto load_stage = [&](int st, int kt) {
        size_t kk = (size_t)kt * 16;
        if (hasA) {
            __pipeline_memcpy_async(&sAh[st][lrA][lh], g_Ah + aoff + kk, 16);
            __pipeline_memcpy_async(&sAl[st][lrA][lh], g_Al + aoff + kk, 16);
            __pipeline_memcpy_async(&sBh[st][lrB1][lh], g_Bh + boff1 + kk, 16);
            __pipeline_memcpy_async(&sBl[st][lrB1][lh], g_Bl + boff1 + kk, 16);
        }
        __pipeline_memcpy_async(&sBh[st][lrB0][lh], g_Bh + boff0 + kk, 16);
        __pipeline_memcpy_async(&sBl[st][lrB0][lh], g_Bl + boff0 + kk, 16);
        __pipeline_commit();
    };

    wmma::fragment<wmma::accumulator, 16, 16, 16, float> acc[2][3];
    for (int i = 0; i < 2; i++) {
        for (int j = 0; j < 3; j++) wmma::fill_fragment(acc[i][j], 0.f);
    }

    load_stage(0, 0);

    for (int kt = 0; kt < NT2; kt++) {
        const int cur = kt & 1;
        __pipeline_wait_prior(0);
        __syncthreads();
        if (kt + 1 < NT2) load_stage(cur ^ 1, kt + 1);

        wmma::fragment<wmma::matrix_b, 16, 16, 16, __nv_bfloat16, wmma::col_major> fbh[3], fbl[3];
        for (int ni = 0; ni < 3; ni++) {
            wmma::load_matrix_sync(fbh[ni], &sBh[cur][wn * 48 + ni * 16][0], RS);
            wmma::load_matrix_sync(fbl[ni], &sBl[cur][wn * 48 + ni * 16][0], RS);
        }
        for (int mi = 0; mi < 2; mi++) {
            wmma::fragment<wmma::matrix_a, 16, 16, 16, __nv_bfloat16, wmma::row_major> fah, fal;
            wmma::load_matrix_sync(fah, &sAh[cur][wm * 32 + mi * 16][0], RS);
            wmma::load_matrix_sync(fal, &sAl[cur][wm * 32 + mi * 16][0], RS);
            for (int ni = 0; ni < 3; ni++) {
                wmma::mma_sync(acc[mi][ni], fah, fbh[ni], acc[mi][ni]);
                wmma::mma_sync(acc[mi][ni], fah, fbl[ni], acc[mi][ni]);
                wmma::mma_sync(acc[mi][ni], fal, fbh[ni], acc[mi][ni]);
            }
        }
    }

    for (int mi = 0; mi < 2; mi++) {
        for (int ni = 0; ni < 3; ni++) {
            size_t r = (size_t)(row0 + wm * 32 + mi * 16);
            size_t cc = (size_t)(cls * NPC + wn * 48 + ni * 16);
            wmma::store_matrix_sync(&g_CM[r * ROWW + cc], acc[mi][ni], ROWW, wmma::mem_row_major);
        }
    }
}

// ---------------- setup: FAC calibration (peak near bin 43.5) ----------------
__global__ void k_facmag() {
    int k = blockIdx.x + KLO;
    int fr = blockIdx.y;
    int tid = threadIdx.x;
    const float* sw = &g_CALSW[fr * NFFT];
    float re = 0.f, im = 0.f;
    for (int n = tid; n < NFFT; n += 128) {
        int m = (k * n) % NFFT;
        float2 t = g_TRIG[m];
        float wx = sw[n];
        re += wx * t.x;
        im += wx * t.y;
    }
    __shared__ float sre[128], sim[128];
    sre[tid] = re; sim[tid] = im; __syncthreads();
    for (int o = 64; o > 0; o >>= 1) {
        if (tid < o) { sre[tid] += sre[tid + o]; sim[tid] += sim[tid + o]; }
        __syncthreads();
    }
    if (tid == 0) g_FMAG[fr * KWIN + blockIdx.x] = sqrtf(sre[0] * sre[0] + sim[0] * sim[0]);
}

// ---------------- merged: FAC reduction + Ec-based norm_inv ----------------
__global__ void k_facnorm() {
    int tid = threadIdx.x;          // 320
    int w = tid >> 5, lane = tid & 31;
    __shared__ float fmx[10];
    __shared__ float srow[ZB];
    if (w < 10) {
        float mx = 0.f;
        for (int k = lane; k < KWIN; k += 32) mx = fmaxf(mx, g_FMAG[w * KWIN + k]);
        for (int o = 16; o > 0; o >>= 1) mx = fmaxf(mx, __shfl_xor_sync(0xffffffff, mx, o));
        if (lane == 0) fmx[w] = mx;
    }
    if (tid < ZB) {
        int r = tid; float s = 0.f;
        for (int c = 0; c < ZB; c++) {
            float slope = (r <= c) ? 27.0f : g_SU0[r];
            float e = fminf(0.025f * (float)(r - c) * slope, 30.0f);
            s += fexp2(e * LOG2_10);
        }
        srow[r] = s;
    }
    __syncthreads();
    if (tid == 0) {
        float total = 0.f;
        for (int fr = 0; fr < 10; fr++) total += fmx[fr];
        g_FAC[0] = exp2f(4.6f * LOG2_10) / (total * 0.1f);
    }
    if (tid < ZB) {
        int r = tid; float t = 0.f;
        for (int c = 0; c < ZB; c++) {
            float slope = (r <= c) ? 27.0f : g_SU0[r];
            float e = fminf(0.025f * (float)(r - c) * slope, 30.0f);
            float ec = fexp2(e * LOG2_10) / srow[c];
            t += fexp2(0.4f * __log2f(ec));
        }
        g_NORMI[r] = fexp2(-2.5f * __log2f(t));
    }
}

// ---------------- |X|^2 (x FAC^2) -> bark energies (+ internal noise) ----------------
__global__ void k_bark() {
    int fb = blockIdx.x;
    int tid = threadIdx.x;
    __shared__ float P[8][768];
    float fac = g_FAC[0];
    float fac2 = fac * fac;
    for (int i = 0; i < 8; i++) {
        int fg = fb * 8 + i;
        const float* crow = &g_CM[(size_t)fg * ROWW];
        for (int j = tid; j < NBINS; j += 128) {
            int k = j + 3;
            int c = k % 9;
            int k0 = (c >= 3) ? c : c + 9;
            int p = (k - k0) / 9;
            float2 v = *(const float2*)&crow[c * NPC + 2 * p];
            P[i][j] = v.x * v.x + v.y * v.y;
        }
    }
    __syncthreads();
    if (tid < ZB) {
        float acc[8] = {0, 0, 0, 0, 0, 0, 0, 0};
        for (int j = 0; j < NBINS; j++) {
            float bv = g_BARK[j * 112 + tid];
            for (int i = 0; i < 8; i++) acc[i] += P[i][j] * bv;
        }
        float wn = g_WN[tid];
        for (int i = 0; i < 8; i++)
            g_UEP[(size_t)(fb * 8 + i) * 112 + tid] = fmaxf(acc[i] * fac2, 1e-12f) + wn;
    }
}

// ---------------- frequency smearing (faithful; MUFU transcendentals) ----------------
__global__ void k_smear() {
    int fg = blockIdx.x;
    int tid = threadIdx.x;
    __shared__ float m2[ZB], Su[ZB], icol[ZB];
    if (tid < ZB) {
        float lg = __log2f(g_UEP[(size_t)fg * 112 + tid]);
        float L = 3.0102999566f * lg;
        m2[tid] = fminf(0.30102999566f * lg, 30.0f);
        Su[tid] = g_SU0[tid] + 0.2f * L;
    }
    __syncthreads();
    if (tid < ZB) {
        int c = tid;
        float colsum = 0.f;
        for (int r = 0; r < ZB; r++) {
            float slope = (r <= c) ? 27.0f : Su[r];
            float e1 = 0.025f * (float)(r - c) * slope;
            float m = fminf(e1, 30.0f) + m2[r];
            colsum += fexp2(m * LOG2_10);
        }
        icol[c] = fexp2(-0.4f * __log2f(colsum));
    }
    __syncthreads();
    if (tid < ZB) {
        int c = tid;
        float acc = 0.f;
        for (int r = 0; r < ZB; r++) {
            float slope = (r <= c) ? 27.0f : Su[r];
            float e1 = 0.025f * (float)(r - c) * slope;
            float m = fminf(e1, 30.0f) + m2[r];
            acc += fexp2(0.4f * LOG2_10 * m) * icol[r];
        }
        float E2 = fexp2(2.5f * __log2f(acc)) * g_NORMI[c];
        int b = fg / NFRAMES, f = fg % NFRAMES;
        g_SM[((size_t)b * ZB + c) * NFRAMES + f] = E2;
    }
}

// ---------------- per-band IIR + max (one row per block: spread across SMs) ---------
__global__ void k_iir(float* __restrict__ out) {
    int idx = blockIdx.x;
    if (threadIdx.x != 0) return;
    int z = idx % ZB;
    float a = g_A[z], b0 = 1.f - a;
    const float* row = &g_SM[(size_t)idx * NFRAMES];
    float* orow = &out[(size_t)idx * NFRAMES];
    float ef = 0.f;
    for (int t = 0; t < NFRAMES; t++) {
        float u = row[t];
        float xin = (t == 0) ? 0.f : u;
        ef = fmaf(a, ef, b0 * xin);
        orow[t] = fmaxf(ef, u);
    }
}

// ---------------- launch ----------------
extern "C" void kernel_launch(void* const* d_in, const int* in_sizes, int n_in,
                              void* d_out, int out_size) {
    const float* pred = (const float*)d_in[0];
    const float* targ = (const float*)d_in[1];
    float* out = (float*)d_out;

    k_tab<<<64, 256>>>();
    k_tw2<<<NCLS * NPC, 128>>>();
    k_fold<<<MTOT, 256>>>(pred, targ);
    k_gemm2<<<dim3(1, MPAD / BM, NCLS), 256>>>();   // 4th launch -> profiled slot
    k_facmag<<<dim3(KWIN, 10), 128>>>();
    k_facnorm<<<1, 320>>>();
    k_bark<<<NFRAMES, 128>>>();
    k_smear<<<MTOT, 128>>>();
    k_iir<<<NBATCH * ZB, 32>>>(out);
}

// round 13
// speedup vs baseline: 1.2910x; 1.2043x over previous
#include <cuda_runtime.h>
#include <cuda_bf16.h>
#include <cuda_pipeline_primitives.h>
#include <mma.h>
#include <math.h>

// ---------------- problem constants ----------------
#define NFFT    1881
#define STEPSZ  941
#define ZB      109
#define NFRAMES 468
#define NBATCH  8
#define MTOT    (NBATCH*NFRAMES)
#define MPAD    3840
#define NBINS   765
#define TLEN    441000
#define LOG2_10 3.321928094887362f
#define KLO     20
#define KHI     71
#define KWIN    (KHI-KLO)
#define RS      24
// CT factorization: 1881 = 9 x 209
#define N2CNT   209
#define KP2     432
#define NT2     (KP2/16)
#define NCLS    9
#define NPC     192
#define ROWW    (NCLS*NPC)
#define BM      64

__device__ __forceinline__ float fexp2(float x) { return __expf(x * 0.6931471805599453f); }

// ---------------- scratch ----------------
__device__ __align__(16) __nv_bfloat16 g_Ah[(size_t)NCLS * MPAD * KP2];
__device__ __align__(16) __nv_bfloat16 g_Al[(size_t)NCLS * MPAD * KP2];
__device__ __align__(16) __nv_bfloat16 g_Bh[NCLS * NPC * KP2];
__device__ __align__(16) __nv_bfloat16 g_Bl[NCLS * NPC * KP2];
__device__ __align__(16) float g_CM[(size_t)MPAD * ROWW];
__device__ __align__(16) float g_BARK[NBINS * 112];
__device__ __align__(16) float g_UEP[MTOT * 112];
__device__ __align__(16) float g_SM[NBATCH * ZB * NFRAMES];
__device__ __align__(16) float2 g_TRIG[NFFT];
__device__ __align__(16) float g_CALSW[10 * NFFT];
__device__ float g_ESC[NBINS];
__device__ float g_W[NFFT];
__device__ float g_FC[ZB], g_SU0[ZB], g_WN[ZB], g_A[ZB], g_NORMI[ZB];
__device__ float g_FMAG[10 * KWIN];
__device__ float g_FAC[1];

// ---------------- setup A: tables + bark matrix (grid-strided) ----------------
__global__ void k_tab() {
    int gt = blockIdx.x * blockDim.x + threadIdx.x;
    int gs = gridDim.x * blockDim.x;
    for (int n = gt; n < NFFT; n += gs)
        g_W[n] = (float)(0.5 * (1.0 - cospi(2.0 * n / 1880.0)));
    for (int m = gt; m < NFFT; m += gs) {
        double ph = 2.0 * (double)m / 1881.0;
        g_TRIG[m] = make_float2((float)cospi(ph), (float)sinpi(ph));
    }
    for (int i = gt; i < 10 * NFFT; i += gs) {
        int fr = i / NFFT, n = i % NFFT;
        int t = fr * STEPSZ + n;
        int p = (t * 2039) % 88200;
        float sv = sinpif((float)p * (1.0f / 44100.0f));
        float wp = 0.5f * (1.0f - cospif((float)(2 * n) * (1.0f / 1881.0f)));
        g_CALSW[i] = wp * sv;
    }
    for (int j = gt; j < NBINS; j += gs) {
        int bin = j + 3;
        float f = 22050.0f * (float)bin / 941.0f;
        float fk = f * 0.001f;
        float lgfk = log2f(fk);
        float Wdb = -2.184f * exp2f(-0.8f * lgfk)
                  + 6.5f * expf(-0.6f * (fk - 3.3f) * (fk - 3.3f))
                  - 0.001f * exp2f(3.6f * lgfk);
        g_ESC[j] = exp2f(Wdb * (LOG2_10 / 20.f)) * (1.0f / 1881.0f);
    }
    for (int idx = gt; idx < NBINS * ZB; idx += gs) {
        int k = idx / ZB, j = idx % ZB;
        double df = 44100.0 / 1881.0;
        int bin = k + 3;
        double blo = bin * df - df / 2.0, bhi = bin * df + df / 2.0;
        double zL = 7.0 * asinh(80.0 / 650.0);
        double felo = 650.0 * sinh((zL + 0.25 * j) / 7.0);
        double fehi = 650.0 * sinh((zL + 0.25 * (j + 1)) / 7.0);
        double ov = fmin(bhi, fehi) - fmax(blo, felo);
        ov = fmax(ov, 0.0) / df;
        g_BARK[k * 112 + j] = (float)ov;
    }
    if (gt < ZB) {
        double zL = 7.0 * asinh(80.0 / 650.0);
        double ze = zL + 0.25 * gt;
        double fcd = 650.0 * sinh((ze + 0.125) / 7.0);
        float fc = (float)fcd;
        g_FC[gt] = fc;
        g_SU0[gt] = -24.0f - 230.0f / fc;
        g_WN[gt] = (float)pow(10.0, 0.4 * 0.364 * pow(fcd / 1000.0, -0.8));
        double tau = 0.008 + 2.2 / fcd;
        g_A[gt] = (float)exp(-4.0 / (187.5 * tau));
    }
}

// ---------------- setup: per-class twiddle matrices B ----------------
__global__ void k_tw2() {
    int gid = blockIdx.x;
    int c = gid / NPC, col = gid - c * NPC;
    int p = col >> 1;
    int k0 = (c >= 3) ? c : c + 9;
    int k = k0 + 9 * p;
    bool valid = (p < 85);
    float sc = valid ? g_ESC[k - 3] : 0.f;
    for (int q = threadIdx.x; q < KP2; q += 128) {
        float v = 0.f;
        if (valid && q < 2 * N2CNT) {
            int n2 = q >> 1;
            float2 t = g_TRIG[(k * n2) % NFFT];
            if ((col & 1) == 0) v = (q & 1) ? t.y : t.x;
            else                v = (q & 1) ? t.x : -t.y;
            v *= sc;
        }
        __nv_bfloat16 h = __float2bfloat16(v);
        float r = v - __bfloat162float(h);
        size_t o = ((size_t)c * NPC + col) * KP2 + q;
        g_Bh[o] = h;
        g_Bl[o] = __float2bfloat16(r);
    }
}

// ---------------- stage 1: window + 9-point fold -> A ----------------
__global__ void k_fold(const float* __restrict__ pred, const float* __restrict__ targ) {
    __shared__ float xw[NFFT];
    int fg = blockIdx.x;
    int tid = threadIdx.x;          // 256
    int b = fg / NFRAMES, f = fg % NFRAMES;
    const float* src = (b < 4) ? pred + (size_t)b * TLEN : targ + (size_t)(b - 4) * TLEN;
    int start = f * STEPSZ;
    for (int n = tid; n < NFFT; n += 256) {
        int s = start + n;
        xw[n] = ((s < TLEN) ? src[s] : 0.f) * g_W[n];
    }
    __syncthreads();
    for (int c = 0; c < NCLS; c++) {
        float2 tw[9];
        #pragma unroll
        for (int n1 = 0; n1 < 9; n1++)
            tw[n1] = g_TRIG[((c * n1) % 9) * N2CNT];
        for (int n2 = tid; n2 < N2CNT; n2 += 256) {
            float yr = 0.f, yi = 0.f;
            #pragma unroll
            for (int n1 = 0; n1 < 9; n1++) {
                float xv = xw[n2 + N2CNT * n1];
                yr = fmaf(xv, tw[n1].x, yr);
                yi = fmaf(-xv, tw[n1].y, yi);
            }
            size_t base = ((size_t)c * MPAD + fg) * KP2 + 2 * n2;
            __nv_bfloat162 h2;
            h2.x = __float2bfloat16(yr);
            h2.y = __float2bfloat16(yi);
            *(__nv_bfloat162*)(g_Ah + base) = h2;
            __nv_bfloat162 l2;
            l2.x = __float2bfloat16(yr - __bfloat162float(h2.x));
            l2.y = __float2bfloat16(yi - __bfloat162float(h2.y));
            *(__nv_bfloat162*)(g_Al + base) = l2;
        }
    }
    if (tid < KP2 - 2 * N2CNT) {
        __nv_bfloat16 z = __float2bfloat16(0.f);
        for (int c = 0; c < NCLS; c++) {
            size_t base = ((size_t)c * MPAD + fg) * KP2 + 2 * N2CNT + tid;
            g_Ah[base] = z;
            g_Al[base] = z;
        }
    }
}

// ---------------- stage 2: split-bf16 tensor GEMM (unchanged from R11) ----------------
__global__ __launch_bounds__(256, 2) void k_gemm2() {
    using namespace nvcuda;
    __shared__ __align__(16) __nv_bfloat16 sAh[2][BM][RS];
    __shared__ __align__(16) __nv_bfloat16 sAl[2][BM][RS];
    __shared__ __align__(16) __nv_bfloat16 sBh[2][NPC][RS];
    __shared__ __align__(16) __nv_bfloat16 sBl[2][NPC][RS];

    const int tid = threadIdx.x;
    const int w = tid >> 5;
    const int wm = w & 1;
    const int wn = w >> 1;
    const int cls = blockIdx.z;
    const int row0 = blockIdx.y * BM;

    const bool hasA = (tid < 128);
    const int lrA = tid >> 1;
    const int lh = (tid & 1) * 8;
    const size_t aoff = ((size_t)cls * MPAD + row0 + (hasA ? lrA : 0)) * KP2 + lh;
    const int lrB0 = tid >> 1;
    const size_t boff0 = ((size_t)cls * NPC + lrB0) * KP2 + lh;
    const int lrB1 = 128 + (tid >> 1);
    const size_t boff1 = ((size_t)cls * NPC + (hasA ? lrB1 : 128)) * KP2 + lh;

    auto load_stage = [&](int st, int kt) {
        size_t kk = (size_t)kt * 16;
        if (hasA) {
            __pipeline_memcpy_async(&sAh[st][lrA][lh], g_Ah + aoff + kk, 16);
            __pipeline_memcpy_async(&sAl[st][lrA][lh], g_Al + aoff + kk, 16);
            __pipeline_memcpy_async(&sBh[st][lrB1][lh], g_Bh + boff1 + kk, 16);
            __pipeline_memcpy_async(&sBl[st][lrB1][lh], g_Bl + boff1 + kk, 16);
        }
        __pipeline_memcpy_async(&sBh[st][lrB0][lh], g_Bh + boff0 + kk, 16);
        __pipeline_memcpy_async(&sBl[st][lrB0][lh], g_Bl + boff0 + kk, 16);
        __pipeline_commit();
    };

    wmma::fragment<wmma::accumulator, 16, 16, 16, float> acc[2][3];
    for (int i = 0; i < 2; i++) {
        for (int j = 0; j < 3; j++) wmma::fill_fragment(acc[i][j], 0.f);
    }

    load_stage(0, 0);

    for (int kt = 0; kt < NT2; kt++) {
        const int cur = kt & 1;
        __pipeline_wait_prior(0);
        __syncthreads();
        if (kt + 1 < NT2) load_stage(cur ^ 1, kt + 1);

        wmma::fragment<wmma::matrix_b, 16, 16, 16, __nv_bfloat16, wmma::col_major> fbh[3], fbl[3];
        for (int ni = 0; ni < 3; ni++) {
            wmma::load_matrix_sync(fbh[ni], &sBh[cur][wn * 48 + ni * 16][0], RS);
            wmma::load_matrix_sync(fbl[ni], &sBl[cur][wn * 48 + ni * 16][0], RS);
        }
        for (int mi = 0; mi < 2; mi++) {
            wmma::fragment<wmma::matrix_a, 16, 16, 16, __nv_bfloat16, wmma::row_major> fah, fal;
            wmma::load_matrix_sync(fah, &sAh[cur][wm * 32 + mi * 16][0], RS);
            wmma::load_matrix_sync(fal, &sAl[cur][wm * 32 + mi * 16][0], RS);
            for (int ni = 0; ni < 3; ni++) {
                wmma::mma_sync(acc[mi][ni], fah, fbh[ni], acc[mi][ni]);
                wmma::mma_sync(acc[mi][ni], fah, fbl[ni], acc[mi][ni]);
                wmma::mma_sync(acc[mi][ni], fal, fbh[ni], acc[mi][ni]);
            }
        }
    }

    for (int mi = 0; mi < 2; mi++) {
        for (int ni = 0; ni < 3; ni++) {
            size_t r = (size_t)(row0 + wm * 32 + mi * 16);
            size_t cc = (size_t)(cls * NPC + wn * 48 + ni * 16);
            wmma::store_matrix_sync(&g_CM[r * ROWW + cc], acc[mi][ni], ROWW, wmma::mem_row_major);
        }
    }
}

// ---------------- setup: FAC calibration ----------------
__global__ void k_facmag() {
    int k = blockIdx.x + KLO;
    int fr = blockIdx.y;
    int tid = threadIdx.x;
    const float* sw = &g_CALSW[fr * NFFT];
    float re = 0.f, im = 0.f;
    for (int n = tid; n < NFFT; n += 128) {
        int m = (k * n) % NFFT;
        float2 t = g_TRIG[m];
        float wx = sw[n];
        re += wx * t.x;
        im += wx * t.y;
    }
    __shared__ float sre[128], sim[128];
    sre[tid] = re; sim[tid] = im; __syncthreads();
    for (int o = 64; o > 0; o >>= 1) {
        if (tid < o) { sre[tid] += sre[tid + o]; sim[tid] += sim[tid + o]; }
        __syncthreads();
    }
    if (tid == 0) g_FMAG[fr * KWIN + blockIdx.x] = sqrtf(sre[0] * sre[0] + sim[0] * sim[0]);
}

// ---------------- merged: FAC reduction + norm_inv ----------------
__global__ void k_facnorm() {
    int tid = threadIdx.x;          // 320
    int w = tid >> 5, lane = tid & 31;
    __shared__ float fmx[10];
    __shared__ float srow[ZB];
    if (w < 10) {
        float mx = 0.f;
        for (int k = lane; k < KWIN; k += 32) mx = fmaxf(mx, g_FMAG[w * KWIN + k]);
        for (int o = 16; o > 0; o >>= 1) mx = fmaxf(mx, __shfl_xor_sync(0xffffffff, mx, o));
        if (lane == 0) fmx[w] = mx;
    }
    if (tid < ZB) {
        int r = tid; float s = 0.f;
        for (int c = 0; c < ZB; c++) {
            float slope = (r <= c) ? 27.0f : g_SU0[r];
            float e = fminf(0.025f * (float)(r - c) * slope, 30.0f);
            s += fexp2(e * LOG2_10);
        }
        srow[r] = s;
    }
    __syncthreads();
    if (tid == 0) {
        float total = 0.f;
        for (int fr = 0; fr < 10; fr++) total += fmx[fr];
        g_FAC[0] = exp2f(4.6f * LOG2_10) / (total * 0.1f);
    }
    if (tid < ZB) {
        int r = tid; float t = 0.f;
        for (int c = 0; c < ZB; c++) {
            float slope = (r <= c) ? 27.0f : g_SU0[r];
            float e = fminf(0.025f * (float)(r - c) * slope, 30.0f);
            float ec = fexp2(e * LOG2_10) / srow[c];
            t += fexp2(0.4f * __log2f(ec));
        }
        g_NORMI[r] = fexp2(-2.5f * __log2f(t));
    }
}

// ---------------- |X|^2 (x FAC^2) -> bark energies: 256 thr, 2 z-groups x 4 frames ----
__global__ void k_bark() {
    int fb = blockIdx.x;
    int tid = threadIdx.x;          // 256
    __shared__ float P[8][768];
    float fac = g_FAC[0];
    float fac2 = fac * fac;
    for (int i = 0; i < 8; i++) {
        int fg = fb * 8 + i;
        const float* crow = &g_CM[(size_t)fg * ROWW];
        for (int j = tid; j < NBINS; j += 256) {
            int k = j + 3;
            int c = k % 9;
            int k0 = (c >= 3) ? c : c + 9;
            int p = (k - k0) / 9;
            float2 v = *(const float2*)&crow[c * NPC + 2 * p];
            P[i][j] = v.x * v.x + v.y * v.y;
        }
    }
    __syncthreads();
    int grp = tid >> 7;             // 0: frames 0-3, 1: frames 4-7
    int z = tid & 127;
    if (z < ZB) {
        int f0 = grp * 4;
        float acc[4] = {0, 0, 0, 0};
        for (int j = 0; j < NBINS; j++) {
            float bv = g_BARK[j * 112 + z];
            #pragma unroll
            for (int i = 0; i < 4; i++) acc[i] += P[f0 + i][j] * bv;
        }
        float wn = g_WN[z];
        for (int i = 0; i < 4; i++)
            g_UEP[(size_t)(fb * 8 + f0 + i) * 112 + z] = fmaxf(acc[i] * fac2, 1e-12f) + wn;
    }
}

// ---------------- frequency smearing: 256 thr, split r-range halves ----------------
__global__ void k_smear() {
    int fg = blockIdx.x;
    int tid = threadIdx.x;          // 256
    __shared__ float m2[ZB], Su[ZB], icol[ZB];
    __shared__ float part[2][ZB];
    int grp = tid >> 7;             // r-half: 0 -> [0,55), 1 -> [55,109)
    int c = tid & 127;
    if (grp == 0 && c < ZB) {
        float lg = __log2f(g_UEP[(size_t)fg * 112 + c]);
        float L = 3.0102999566f * lg;
        m2[c] = fminf(0.30102999566f * lg, 30.0f);
        Su[c] = g_SU0[c] + 0.2f * L;
    }
    __syncthreads();
    int r0 = grp ? 55 : 0;
    int r1 = grp ? ZB : 55;
    if (c < ZB) {
        float s = 0.f;
        for (int r = r0; r < r1; r++) {
            float slope = (r <= c) ? 27.0f : Su[r];
            float e1 = 0.025f * (float)(r - c) * slope;
            float m = fminf(e1, 30.0f) + m2[r];
            s += fexp2(m * LOG2_10);
        }
        part[grp][c] = s;
    }
    __syncthreads();
    if (grp == 0 && c < ZB)
        icol[c] = fexp2(-0.4f * __log2f(part[0][c] + part[1][c]));
    __syncthreads();
    if (c < ZB) {
        float a = 0.f;
        for (int r = r0; r < r1; r++) {
            float slope = (r <= c) ? 27.0f : Su[r];
            float e1 = 0.025f * (float)(r - c) * slope;
            float m = fminf(e1, 30.0f) + m2[r];
            a += fexp2(0.4f * LOG2_10 * m) * icol[r];
        }
        part[grp][c] = a;
    }
    __syncthreads();
    if (grp == 0 && c < ZB) {
        float acc = part[0][c] + part[1][c];
        float E2 = fexp2(2.5f * __log2f(acc)) * g_NORMI[c];
        int b = fg / NFRAMES, f = fg % NFRAMES;
        g_SM[((size_t)b * ZB + c) * NFRAMES + f] = E2;
    }
}

// ---------------- per-band IIR + max: smem-staged recurrence ----------------
__global__ void k_iir(float* __restrict__ out) {
    __shared__ float row[NFRAMES];
    __shared__ float orow[NFRAMES];
    int idx = blockIdx.x;
    int tid = threadIdx.x;          // 64
    const float* src = &g_SM[(size_t)idx * NFRAMES];
    for (int t = tid; t < NFRAMES; t += 64) row[t] = src[t];
    __syncthreads();
    if (tid == 0) {
        int z = idx % ZB;
        float a = g_A[z], b0 = 1.f - a;
        float ef = 0.f;
        for (int t = 0; t < NFRAMES; t++) {
            float u = row[t];
            float xin = (t == 0) ? 0.f : u;
            ef = fmaf(a, ef, b0 * xin);
            orow[t] = fmaxf(ef, u);
        }
    }
    __syncthreads();
    float* dst = &out[(size_t)idx * NFRAMES];
    for (int t = tid; t < NFRAMES; t += 64) dst[t] = orow[t];
}

// ---------------- launch ----------------
extern "C" void kernel_launch(void* const* d_in, const int* in_sizes, int n_in,
                              void* d_out, int out_size) {
    const float* pred = (const float*)d_in[0];
    const float* targ = (const float*)d_in[1];
    float* out = (float*)d_out;

    k_tab<<<64, 256>>>();
    k_tw2<<<NCLS * NPC, 128>>>();
    k_fold<<<MTOT, 256>>>(pred, targ);
    k_gemm2<<<dim3(1, MPAD / BM, NCLS), 256>>>();   // 4th launch -> profiled slot
    k_facmag<<<dim3(KWIN, 10), 128>>>();
    k_facnorm<<<1, 320>>>();
    k_bark<<<NFRAMES, 256>>>();
    k_smear<<<MTOT, 256>>>();
    k_iir<<<NBATCH * ZB, 64>>>(out);
}